// round 1
// baseline (speedup 1.0000x reference)
#include <cuda_runtime.h>
#include <cuda_bf16.h>

// Problem constants
#define BATCH 32
#define SEQ 2
#define CHAN 7
#define HM_C 3
#define HH 256
#define WW 256
#define HW (HH*WW)                 // 65536
#define HM_TOTAL (HM_C*HW)         // 196608
#define TOPK_N 100
#define NMS_N 200                  // SEQ*TOPK
#define CAND_CAP 4096

// Intermediate detections (device globals: allocation-free scratch)
__device__ float g_boxes[BATCH*SEQ*TOPK_N*4];
__device__ float g_scores[BATCH*SEQ*TOPK_N];
__device__ int   g_cls[BATCH*SEQ*TOPK_N];

static __device__ __forceinline__ unsigned order_f32(float f) {
    unsigned u = __float_as_uint(f);
    return (u & 0x80000000u) ? ~u : (u | 0x80000000u);
}

// ---------------------------------------------------------------------------
// Kernel A: per-(b,s) top-100 over sigmoid heatmap + box decode.
// grid = 64 blocks (one per (b,s)), 512 threads.
// ---------------------------------------------------------------------------
__global__ __launch_bounds__(512)
void topk_decode_kernel(const float* __restrict__ x) {
    const int bs = blockIdx.x;                       // 0..63
    const float* __restrict__ base = x + (size_t)bs * CHAN * HW;

    __shared__ int hist[2048];
    __shared__ int gsum[64];
    __shared__ int s_thrbin;
    __shared__ int s_n;
    __shared__ unsigned long long key[CAND_CAP];     // 32 KB

    const int tid = threadIdx.x;

    for (int i = tid; i < 2048; i += blockDim.x) hist[i] = 0;
    if (tid == 0) s_n = 0;
    __syncthreads();

    // ---- Pass 1: histogram of order-mapped bits (top 11 bits), warp-aggregated
    const int NV4 = HM_TOTAL / 4;                    // 49152, divisible by 512
    for (int e = tid; e < NV4; e += blockDim.x) {
        float4 f4 = reinterpret_cast<const float4*>(base)[e];
        #pragma unroll
        for (int c = 0; c < 4; ++c) {
            float f = (&f4.x)[c];
            int bin = (int)(order_f32(f) >> 21);
            unsigned mask = __match_any_sync(0xffffffffu, bin);
            if ((tid & 31) == (__ffs(mask) - 1))
                atomicAdd(&hist[bin], __popc(mask));
        }
    }
    __syncthreads();

    // ---- Find threshold bin: largest t with suffix-count >= 100
    if (tid < 64) {
        int s = 0;
        #pragma unroll
        for (int k = 0; k < 32; ++k) s += hist[tid*32 + k];
        gsum[tid] = s;
    }
    __syncthreads();
    if (tid == 0) {
        int cum = 0, g;
        for (g = 63; g >= 0; --g) {
            if (cum + gsum[g] >= TOPK_N) break;
            cum += gsum[g];
        }
        int t;
        for (t = g*32 + 31; t >= g*32; --t) {
            cum += hist[t];
            if (cum >= TOPK_N) break;
        }
        s_thrbin = t;
    }
    __syncthreads();
    const unsigned thr = (unsigned)s_thrbin << 21;

    // ---- Pass 2: collect candidates; key = (sigmoid_bits << 32) | ~idx
    for (int e = tid; e < NV4; e += blockDim.x) {
        float4 f4 = reinterpret_cast<const float4*>(base)[e];
        #pragma unroll
        for (int c = 0; c < 4; ++c) {
            float f = (&f4.x)[c];
            if (order_f32(f) >= thr) {
                int p = atomicAdd(&s_n, 1);
                if (p < CAND_CAP) {
                    unsigned idx = 4u*e + c;
                    float sig = 1.0f / (1.0f + expf(-f));
                    key[p] = ((unsigned long long)__float_as_uint(sig) << 32)
                           | (unsigned long long)(0xFFFFFFFFu - idx);
                }
            }
        }
    }
    __syncthreads();
    int n = s_n; if (n > CAND_CAP) n = CAND_CAP;

    // ---- Bitonic sort descending (pad with 0)
    int P = 128; while (P < n) P <<= 1;
    for (int i = n + tid; i < P; i += blockDim.x) key[i] = 0ULL;
    __syncthreads();
    for (int k = 2; k <= P; k <<= 1) {
        for (int j = k >> 1; j > 0; j >>= 1) {
            for (int i = tid; i < P; i += blockDim.x) {
                int ixj = i ^ j;
                if (ixj > i) {
                    unsigned long long a = key[i], b = key[ixj];
                    bool up = ((i & k) == 0);        // descending
                    if (up ? (a < b) : (a > b)) { key[i] = b; key[ixj] = a; }
                }
            }
            __syncthreads();
        }
    }

    // ---- Decode top 100
    if (tid < TOPK_N) {
        unsigned long long K = key[tid];
        float score = __uint_as_float((unsigned)(K >> 32));
        unsigned idx = 0xFFFFFFFFu - (unsigned)(K & 0xFFFFFFFFu);
        if (!(score > 0.1f)) score = 0.0f;
        int cls = (int)(idx >> 16);                  // / 65536
        int rem = (int)(idx & 65535u);
        float ys = (float)(rem >> 8);
        float xs = (float)(rem & 255);
        float offx = base[3*HW + rem];
        float offy = base[4*HW + rem];
        float bw   = base[5*HW + rem] * 4.0f;
        float bh   = base[6*HW + rem] * 4.0f;
        float cx = (xs + offx) * 4.0f;
        float cy = (ys + offy) * 4.0f;
        int o = bs*TOPK_N + tid;
        g_boxes[o*4+0] = cx - bw*0.5f;
        g_boxes[o*4+1] = cy - bh*0.5f;
        g_boxes[o*4+2] = cx + bw*0.5f;
        g_boxes[o*4+3] = cy + bh*0.5f;
        g_scores[o] = score;
        g_cls[o]   = cls;
    }
}

// ---------------------------------------------------------------------------
// Kernel B: sequential soft-NMS per batch. grid = 32 blocks, 256 threads.
// ---------------------------------------------------------------------------
__global__ __launch_bounds__(256)
void softnms_kernel(float* __restrict__ out) {
    const int b = blockIdx.x;                        // 0..31
    const int tid = threadIdx.x;

    __shared__ float sx1[NMS_N], sy1[NMS_N], sx2[NMS_N], sy2[NMS_N], ssc[NMS_N];
    __shared__ int   sidx[NMS_N], scls[NMS_N];
    __shared__ unsigned long long part[8];
    __shared__ float sbi[4];

    if (tid < NMS_N) {
        int src = b*NMS_N + tid;                     // contiguous over (s, k)
        sx1[tid] = g_boxes[src*4+0];
        sy1[tid] = g_boxes[src*4+1];
        sx2[tid] = g_boxes[src*4+2];
        sy2[tid] = g_boxes[src*4+3];
        ssc[tid] = g_scores[src];
        scls[tid] = g_cls[src];
        sidx[tid] = tid;
    }
    __syncthreads();

    for (int i = 0; i < NMS_N; ++i) {
        // argmax over pos >= i, first-max wins ties (pack ~pos in low bits)
        unsigned long long kk = 0ULL;
        if (tid < NMS_N && tid >= i)
            kk = ((unsigned long long)__float_as_uint(ssc[tid]) << 32)
               | (unsigned long long)(0xFFFFFFFFu - (unsigned)tid);
        #pragma unroll
        for (int o = 16; o > 0; o >>= 1) {
            unsigned long long other = __shfl_down_sync(0xffffffffu, kk, o);
            if (other > kk) kk = other;
        }
        if ((tid & 31) == 0) part[tid >> 5] = kk;
        __syncthreads();
        if (tid == 0) {
            unsigned long long best = part[0];
            #pragma unroll
            for (int w = 1; w < 8; ++w) if (part[w] > best) best = part[w];
            int m = (int)(0xFFFFFFFFu - (unsigned)(best & 0xFFFFFFFFu));
            if (m != i) {
                float t;
                t = sx1[i]; sx1[i] = sx1[m]; sx1[m] = t;
                t = sy1[i]; sy1[i] = sy1[m]; sy1[m] = t;
                t = sx2[i]; sx2[i] = sx2[m]; sx2[m] = t;
                t = sy2[i]; sy2[i] = sy2[m]; sy2[m] = t;
                t = ssc[i]; ssc[i] = ssc[m]; ssc[m] = t;
                int ti = sidx[i]; sidx[i] = sidx[m]; sidx[m] = ti;
            }
            sbi[0] = sx1[i]; sbi[1] = sy1[i]; sbi[2] = sx2[i]; sbi[3] = sy2[i];
        }
        __syncthreads();
        const float bx1 = sbi[0], by1 = sbi[1], bx2 = sbi[2], by2 = sbi[3];
        const float area_i = (bx2 - bx1 + 1.0f) * (by2 - by1 + 1.0f);
        if (tid < NMS_N && tid > i) {
            float x1 = sx1[tid], y1 = sy1[tid], x2 = sx2[tid], y2 = sy2[tid];
            float area = (x2 - x1 + 1.0f) * (y2 - y1 + 1.0f);
            float xx1 = fmaxf(bx1, x1), yy1 = fmaxf(by1, y1);
            float xx2 = fminf(bx2, x2), yy2 = fminf(by2, y2);
            float inter = fmaxf(0.0f, xx2 - xx1 + 1.0f) * fmaxf(0.0f, yy2 - yy1 + 1.0f);
            float iou = inter / (area_i + area - inter);
            float w = expf(-(iou * iou) * 2.0f);     // / SIGMA (=0.5)
            ssc[tid] = w * ssc[tid];
        }
        __syncthreads();
    }

    // Outputs: boxes[32,200,4] | cls[32,200] | scores[32,200] | keep[32,200]
    if (tid < NMS_N) {
        int j = b*NMS_N + tid;
        out[j*4+0] = sx1[tid];
        out[j*4+1] = sy1[tid];
        out[j*4+2] = sx2[tid];
        out[j*4+3] = sy2[tid];
        float sc = ssc[tid];
        out[BATCH*NMS_N*4           + j] = (float)scls[sidx[tid]];
        out[BATCH*NMS_N*4 + BATCH*NMS_N   + j] = sc;
        out[BATCH*NMS_N*4 + 2*BATCH*NMS_N + j] = (sc > 0.1f) ? 1.0f : 0.0f;
    }
}

extern "C" void kernel_launch(void* const* d_in, const int* in_sizes, int n_in,
                              void* d_out, int out_size) {
    const float* x = (const float*)d_in[0];
    float* out = (float*)d_out;
    topk_decode_kernel<<<BATCH*SEQ, 512>>>(x);
    softnms_kernel<<<BATCH, 256>>>(out);
}